// round 1
// baseline (speedup 1.0000x reference)
#include <cuda_runtime.h>
#include <math.h>

#define DIM 4096
#define BATCH 8192
#define NUM_LAYERS 6
#define NTHREADS 256
#define ROWS_PER_BLOCK 4
#define VPT 4  // float4 per thread: 256 * 4 * 4 = 4096 floats

// g_stats layout: [0..2] inv_norm(E,C,N); [3..5] G00,G11,G22; [6..8] G01,G02,G12
__device__ float g_stats[9];

__device__ __forceinline__ float dot4(float4 a, float4 b) {
    return a.x * b.x + a.y * b.y + a.z * b.z + a.w * b.w;
}

// ---------------------------------------------------------------------------
// Kernel 0: anchor norms + normalized Gram matrix (one block)
// ---------------------------------------------------------------------------
__global__ void anchor_stats_kernel(const float* __restrict__ aE,
                                    const float* __restrict__ aC,
                                    const float* __restrict__ aN) {
    __shared__ float red[6][NTHREADS / 32];
    float s[6] = {0.f, 0.f, 0.f, 0.f, 0.f, 0.f};
    for (int i = threadIdx.x; i < DIM; i += NTHREADS) {
        float e = aE[i], c = aC[i], n = aN[i];
        s[0] += e * e; s[1] += c * c; s[2] += n * n;
        s[3] += e * c; s[4] += e * n; s[5] += c * n;
    }
#pragma unroll
    for (int off = 16; off; off >>= 1) {
#pragma unroll
        for (int j = 0; j < 6; j++) s[j] += __shfl_xor_sync(0xffffffffu, s[j], off);
    }
    int warp = threadIdx.x >> 5, lane = threadIdx.x & 31;
    if (lane == 0) {
#pragma unroll
        for (int j = 0; j < 6; j++) red[j][warp] = s[j];
    }
    __syncthreads();
    if (threadIdx.x == 0) {
        float d[6];
#pragma unroll
        for (int j = 0; j < 6; j++) {
            float v = 0.f;
#pragma unroll
            for (int w = 0; w < NTHREADS / 32; w++) v += red[j][w];
            d[j] = v;
        }
        float i0 = 1.0f / fmaxf(sqrtf(d[0]), 1e-12f);
        float i1 = 1.0f / fmaxf(sqrtf(d[1]), 1e-12f);
        float i2 = 1.0f / fmaxf(sqrtf(d[2]), 1e-12f);
        g_stats[0] = i0; g_stats[1] = i1; g_stats[2] = i2;
        g_stats[3] = d[0] * i0 * i0;   // G00 = dirE.dirE
        g_stats[4] = d[1] * i1 * i1;   // G11
        g_stats[5] = d[2] * i2 * i2;   // G22
        g_stats[6] = d[3] * i0 * i1;   // G01 = dirE.dirC
        g_stats[7] = d[4] * i0 * i2;   // G02 = dirE.dirN
        g_stats[8] = d[5] * i1 * i2;   // G12 = dirC.dirN
    }
}

// ---------------------------------------------------------------------------
// Kernel 1: fused 6-layer collapse. One block handles ROWS_PER_BLOCK rows.
// Per row: dot products -> scalar 6-layer recurrence -> linear combo write.
// ---------------------------------------------------------------------------
__global__ __launch_bounds__(NTHREADS, 2)
void collapse_kernel(const float* __restrict__ h0,
                     const float* __restrict__ aE,
                     const float* __restrict__ aC,
                     const float* __restrict__ aN,
                     float* __restrict__ out) {
    const int tid = threadIdx.x;

    // Anchor slices live in registers for the whole block (48 regs).
    float4 e[VPT], cvv[VPT], nvv[VPT];
#pragma unroll
    for (int i = 0; i < VPT; i++) {
        int idx = tid + i * NTHREADS;
        e[i]   = __ldg(((const float4*)aE) + idx);
        cvv[i] = __ldg(((const float4*)aC) + idx);
        nvv[i] = __ldg(((const float4*)aN) + idx);
    }

    const float invn0 = g_stats[0], invn1 = g_stats[1], invn2 = g_stats[2];
    const float G00 = g_stats[3], G11 = g_stats[4], G22 = g_stats[5];
    const float G01 = g_stats[6], G02 = g_stats[7], G12 = g_stats[8];

    __shared__ float red[4][NTHREADS / 32];
    __shared__ float bc[4];

    float* outH = out;
    float* outA = out + (size_t)BATCH * DIM;
    float* outD = outA + (size_t)NUM_LAYERS * BATCH * 3;
    float* outT = outD + (size_t)NUM_LAYERS * BATCH * 3;

    const int b0 = blockIdx.x * ROWS_PER_BLOCK;

    // Preload first row (streaming hint: read-once data)
    float4 h[VPT];
    {
        const float4* hrow = (const float4*)(h0 + (size_t)b0 * DIM);
#pragma unroll
        for (int i = 0; i < VPT; i++) h[i] = __ldcs(hrow + tid + i * NTHREADS);
    }

    for (int r = 0; r < ROWS_PER_BLOCK; r++) {
        const int b = b0 + r;

        // partial sums: ||h||^2, h.aE, h.aC, h.aN
        float shh = 0.f, s0 = 0.f, s1 = 0.f, s2 = 0.f;
#pragma unroll
        for (int i = 0; i < VPT; i++) {
            shh += dot4(h[i], h[i]);
            s0  += dot4(h[i], e[i]);
            s1  += dot4(h[i], cvv[i]);
            s2  += dot4(h[i], nvv[i]);
        }

        // software prefetch of next row (overlaps reduction+recurrence+store)
        float4 hn[VPT];
        if (r + 1 < ROWS_PER_BLOCK) {
            const float4* hrow = (const float4*)(h0 + (size_t)(b + 1) * DIM);
#pragma unroll
            for (int i = 0; i < VPT; i++) hn[i] = __ldcs(hrow + tid + i * NTHREADS);
        }

        // block reduction of 4 scalars
#pragma unroll
        for (int off = 16; off; off >>= 1) {
            shh += __shfl_xor_sync(0xffffffffu, shh, off);
            s0  += __shfl_xor_sync(0xffffffffu, s0, off);
            s1  += __shfl_xor_sync(0xffffffffu, s1, off);
            s2  += __shfl_xor_sync(0xffffffffu, s2, off);
        }
        const int warp = tid >> 5, lane = tid & 31;
        if (lane == 0) { red[0][warp] = shh; red[1][warp] = s0; red[2][warp] = s1; red[3][warp] = s2; }
        __syncthreads();
        if (tid < 4) {
            float v = 0.f;
#pragma unroll
            for (int w = 0; w < NTHREADS / 32; w++) v += red[tid][w];
            bc[tid] = v;
        }
        __syncthreads();

        // --- scalar 6-layer recurrence (all threads, redundant + uniform) ---
        float hh = bc[0];
        float a0 = bc[1] * invn0, a1 = bc[2] * invn1, a2 = bc[3] * invn2;
        float ch = 1.f, c0 = 0.f, c1 = 0.f, c2 = 0.f;

#pragma unroll
        for (int l = 0; l < NUM_LAYERS; l++) {
            float invh = 1.0f / fmaxf(sqrtf(hh), 1e-12f);
            float al0 = a0 * invh, al1 = a1 * invh, al2 = a2 * invh;
            float dv0 = 1.f - al0, dv1 = 1.f - al1, dv2 = 1.f - al2;
            if (tid == 0) {
                size_t o = ((size_t)l * BATCH + b) * 3;
                outA[o] = al0; outA[o + 1] = al1; outA[o + 2] = al2;
                outD[o] = dv0; outD[o + 1] = dv1; outD[o + 2] = dv2;
                outT[o] = fmaxf(dv0, 0.f); outT[o + 1] = fmaxf(dv1, 0.f); outT[o + 2] = fmaxf(dv2, 0.f);
            }
            // coef_k = s_k * div_k / max(||h - dir_k||, eps)
            float k0 = 0.10f * dv0 / fmaxf(sqrtf(fmaxf(hh - 2.f * a0 + G00, 0.f)), 1e-12f);
            float k1 = 0.10f * dv1 / fmaxf(sqrtf(fmaxf(hh - 2.f * a1 + G11, 0.f)), 1e-12f);
            float k2 = 0.05f * dv2 / fmaxf(sqrtf(fmaxf(hh - 2.f * a2 + G22, 0.f)), 1e-12f);
            float alpha = 1.f - (k0 + k1 + k2);

            float na0 = alpha * a0 + k0 * G00 + k1 * G01 + k2 * G02;
            float na1 = alpha * a1 + k0 * G01 + k1 * G11 + k2 * G12;
            float na2 = alpha * a2 + k0 * G02 + k1 * G12 + k2 * G22;
            float cross = k0 * k0 * G00 + k1 * k1 * G11 + k2 * k2 * G22
                        + 2.f * (k0 * k1 * G01 + k0 * k2 * G02 + k1 * k2 * G12);
            float nhh = alpha * alpha * hh
                      + 2.f * alpha * (k0 * a0 + k1 * a1 + k2 * a2) + cross;

            ch *= alpha;
            c0 = alpha * c0 + k0;
            c1 = alpha * c1 + k1;
            c2 = alpha * c2 + k2;
            hh = fmaxf(nhh, 0.f);
            a0 = na0; a1 = na1; a2 = na2;

            // norm clamp (uniform branch)
            float nn = sqrtf(hh);
            if (nn > 10.0f) {
                float sc = 10.0f / (nn + 1e-8f);
                ch *= sc; c0 *= sc; c1 *= sc; c2 *= sc;
                a0 *= sc; a1 *= sc; a2 *= sc;
                hh *= sc * sc;
            }
        }

        // --- epilogue: h_final = ch*h0 + sum_k (c_k * inv_n_k) * anchor_k ---
        float bE = c0 * invn0, bC = c1 * invn1, bN = c2 * invn2;
        float4* orow = (float4*)(outH + (size_t)b * DIM);
#pragma unroll
        for (int i = 0; i < VPT; i++) {
            float4 o;
            o.x = ch * h[i].x + bE * e[i].x + bC * cvv[i].x + bN * nvv[i].x;
            o.y = ch * h[i].y + bE * e[i].y + bC * cvv[i].y + bN * nvv[i].y;
            o.z = ch * h[i].z + bE * e[i].z + bC * cvv[i].z + bN * nvv[i].z;
            o.w = ch * h[i].w + bE * e[i].w + bC * cvv[i].w + bN * nvv[i].w;
            __stcs(orow + tid + i * NTHREADS, o);
        }

        if (r + 1 < ROWS_PER_BLOCK) {
#pragma unroll
            for (int i = 0; i < VPT; i++) h[i] = hn[i];
        }
        __syncthreads();
    }
}

extern "C" void kernel_launch(void* const* d_in, const int* in_sizes, int n_in,
                              void* d_out, int out_size) {
    const float* h0 = (const float*)d_in[0];
    const float* aE = (const float*)d_in[1];
    const float* aC = (const float*)d_in[2];
    const float* aN = (const float*)d_in[3];
    float* out = (float*)d_out;

    anchor_stats_kernel<<<1, NTHREADS>>>(aE, aC, aN);
    collapse_kernel<<<BATCH / ROWS_PER_BLOCK, NTHREADS>>>(h0, aE, aC, aN, out);
}

// round 2
// speedup vs baseline: 1.2095x; 1.2095x over previous
#include <cuda_runtime.h>
#include <math.h>

#define DIM 4096
#define BATCH 8192
#define NUM_LAYERS 6
#define NTHREADS 256
#define VPT 4  // float4 per thread: 256 * 4 * 4 = 4096 floats

// g_stats layout: [0..2] inv_norm(E,C,N); [3..5] G00,G11,G22; [6..8] G01,G02,G12
__device__ float g_stats[9];

__device__ __forceinline__ float dot4(float4 a, float4 b) {
    return a.x * b.x + a.y * b.y + a.z * b.z + a.w * b.w;
}

// ---------------------------------------------------------------------------
// Kernel 0: anchor norms + normalized Gram matrix (one block, vectorized)
// ---------------------------------------------------------------------------
__global__ void anchor_stats_kernel(const float* __restrict__ aE,
                                    const float* __restrict__ aC,
                                    const float* __restrict__ aN) {
    __shared__ float red[6][NTHREADS / 32];
    float s[6] = {0.f, 0.f, 0.f, 0.f, 0.f, 0.f};
    const float4* e4 = (const float4*)aE;
    const float4* c4 = (const float4*)aC;
    const float4* n4 = (const float4*)aN;
#pragma unroll
    for (int i = 0; i < VPT; i++) {
        int idx = threadIdx.x + i * NTHREADS;
        float4 e = __ldg(e4 + idx);
        float4 c = __ldg(c4 + idx);
        float4 n = __ldg(n4 + idx);
        s[0] += dot4(e, e); s[1] += dot4(c, c); s[2] += dot4(n, n);
        s[3] += dot4(e, c); s[4] += dot4(e, n); s[5] += dot4(c, n);
    }
#pragma unroll
    for (int off = 16; off; off >>= 1) {
#pragma unroll
        for (int j = 0; j < 6; j++) s[j] += __shfl_xor_sync(0xffffffffu, s[j], off);
    }
    int warp = threadIdx.x >> 5, lane = threadIdx.x & 31;
    if (lane == 0) {
#pragma unroll
        for (int j = 0; j < 6; j++) red[j][warp] = s[j];
    }
    __syncthreads();
    if (threadIdx.x == 0) {
        float d[6];
#pragma unroll
        for (int j = 0; j < 6; j++) {
            float v = 0.f;
#pragma unroll
            for (int w = 0; w < NTHREADS / 32; w++) v += red[j][w];
            d[j] = v;
        }
        float i0 = 1.0f / fmaxf(sqrtf(d[0]), 1e-12f);
        float i1 = 1.0f / fmaxf(sqrtf(d[1]), 1e-12f);
        float i2 = 1.0f / fmaxf(sqrtf(d[2]), 1e-12f);
        g_stats[0] = i0; g_stats[1] = i1; g_stats[2] = i2;
        g_stats[3] = d[0] * i0 * i0;   // G00
        g_stats[4] = d[1] * i1 * i1;   // G11
        g_stats[5] = d[2] * i2 * i2;   // G22
        g_stats[6] = d[3] * i0 * i1;   // G01
        g_stats[7] = d[4] * i0 * i2;   // G02
        g_stats[8] = d[5] * i1 * i2;   // G12
    }
}

// ---------------------------------------------------------------------------
// Kernel 1: fused 6-layer collapse. One block = one row. Anchors from L1.
// ---------------------------------------------------------------------------
__global__ __launch_bounds__(NTHREADS, 4)
void collapse_kernel(const float* __restrict__ h0,
                     const float* __restrict__ aE,
                     const float* __restrict__ aC,
                     const float* __restrict__ aN,
                     float* __restrict__ out) {
    const int tid = threadIdx.x;
    const int b = blockIdx.x;

    __shared__ float red[4][NTHREADS / 32];

    float* outH = out;
    float* outA = out + (size_t)BATCH * DIM;
    float* outD = outA + (size_t)NUM_LAYERS * BATCH * 3;
    float* outT = outD + (size_t)NUM_LAYERS * BATCH * 3;

    const float4* hrow = (const float4*)(h0 + (size_t)b * DIM);
    const float4* e4 = (const float4*)aE;
    const float4* c4 = (const float4*)aC;
    const float4* n4 = (const float4*)aN;

    // h0 row lives in registers for the whole kernel (read-once: streaming hint)
    float4 h[VPT];
#pragma unroll
    for (int i = 0; i < VPT; i++) h[i] = __ldcs(hrow + tid + i * NTHREADS);

    // dot phase: anchors reloaded from L1/L2 (48KB, resident after first wave)
    float shh = 0.f, s0 = 0.f, s1 = 0.f, s2 = 0.f;
#pragma unroll
    for (int i = 0; i < VPT; i++) {
        int idx = tid + i * NTHREADS;
        float4 e = __ldg(e4 + idx);
        float4 c = __ldg(c4 + idx);
        float4 n = __ldg(n4 + idx);
        shh += dot4(h[i], h[i]);
        s0  += dot4(h[i], e);
        s1  += dot4(h[i], c);
        s2  += dot4(h[i], n);
    }

    // block reduction: warp shuffle + single barrier, all threads do final sum
#pragma unroll
    for (int off = 16; off; off >>= 1) {
        shh += __shfl_xor_sync(0xffffffffu, shh, off);
        s0  += __shfl_xor_sync(0xffffffffu, s0, off);
        s1  += __shfl_xor_sync(0xffffffffu, s1, off);
        s2  += __shfl_xor_sync(0xffffffffu, s2, off);
    }
    const int warp = tid >> 5, lane = tid & 31;
    if (lane == 0) { red[0][warp] = shh; red[1][warp] = s0; red[2][warp] = s1; red[3][warp] = s2; }
    __syncthreads();
    {
        float v0 = 0.f, v1 = 0.f, v2 = 0.f, v3 = 0.f;
#pragma unroll
        for (int w = 0; w < NTHREADS / 32; w++) {
            v0 += red[0][w]; v1 += red[1][w]; v2 += red[2][w]; v3 += red[3][w];
        }
        shh = v0; s0 = v1; s1 = v2; s2 = v3;
    }

    const float invn0 = g_stats[0], invn1 = g_stats[1], invn2 = g_stats[2];
    const float G00 = g_stats[3], G11 = g_stats[4], G22 = g_stats[5];
    const float G01 = g_stats[6], G02 = g_stats[7], G12 = g_stats[8];

    // --- scalar 6-layer recurrence (redundant, uniform across threads) ---
    float hh = shh;
    float a0 = s0 * invn0, a1 = s1 * invn1, a2 = s2 * invn2;
    float ch = 1.f, c0 = 0.f, c1 = 0.f, c2 = 0.f;

#pragma unroll
    for (int l = 0; l < NUM_LAYERS; l++) {
        float invh = 1.0f / fmaxf(sqrtf(hh), 1e-12f);
        float al0 = a0 * invh, al1 = a1 * invh, al2 = a2 * invh;
        float dv0 = 1.f - al0, dv1 = 1.f - al1, dv2 = 1.f - al2;
        if (tid == 0) {
            size_t o = ((size_t)l * BATCH + b) * 3;
            outA[o] = al0; outA[o + 1] = al1; outA[o + 2] = al2;
            outD[o] = dv0; outD[o + 1] = dv1; outD[o + 2] = dv2;
            outT[o] = fmaxf(dv0, 0.f); outT[o + 1] = fmaxf(dv1, 0.f); outT[o + 2] = fmaxf(dv2, 0.f);
        }
        // coef_k = s_k * div_k / max(||h - dir_k||, eps)
        float k0 = 0.10f * dv0 / fmaxf(sqrtf(fmaxf(hh - 2.f * a0 + G00, 0.f)), 1e-12f);
        float k1 = 0.10f * dv1 / fmaxf(sqrtf(fmaxf(hh - 2.f * a1 + G11, 0.f)), 1e-12f);
        float k2 = 0.05f * dv2 / fmaxf(sqrtf(fmaxf(hh - 2.f * a2 + G22, 0.f)), 1e-12f);
        float alpha = 1.f - (k0 + k1 + k2);

        float na0 = alpha * a0 + k0 * G00 + k1 * G01 + k2 * G02;
        float na1 = alpha * a1 + k0 * G01 + k1 * G11 + k2 * G12;
        float na2 = alpha * a2 + k0 * G02 + k1 * G12 + k2 * G22;
        float cross = k0 * k0 * G00 + k1 * k1 * G11 + k2 * k2 * G22
                    + 2.f * (k0 * k1 * G01 + k0 * k2 * G02 + k1 * k2 * G12);
        float nhh = alpha * alpha * hh
                  + 2.f * alpha * (k0 * a0 + k1 * a1 + k2 * a2) + cross;

        ch *= alpha;
        c0 = alpha * c0 + k0;
        c1 = alpha * c1 + k1;
        c2 = alpha * c2 + k2;
        hh = fmaxf(nhh, 0.f);
        a0 = na0; a1 = na1; a2 = na2;

        // norm clamp (uniform branch)
        float nn = sqrtf(hh);
        if (nn > 10.0f) {
            float sc = 10.0f / (nn + 1e-8f);
            ch *= sc; c0 *= sc; c1 *= sc; c2 *= sc;
            a0 *= sc; a1 *= sc; a2 *= sc;
            hh *= sc * sc;
        }
    }

    // --- epilogue: h_final = ch*h0 + sum_k (c_k * inv_n_k) * anchor_k ---
    float bE = c0 * invn0, bC = c1 * invn1, bN = c2 * invn2;
    float4* orow = (float4*)(outH + (size_t)b * DIM);
#pragma unroll
    for (int i = 0; i < VPT; i++) {
        int idx = tid + i * NTHREADS;
        float4 e = __ldg(e4 + idx);
        float4 c = __ldg(c4 + idx);
        float4 n = __ldg(n4 + idx);
        float4 o;
        o.x = ch * h[i].x + bE * e.x + bC * c.x + bN * n.x;
        o.y = ch * h[i].y + bE * e.y + bC * c.y + bN * n.y;
        o.z = ch * h[i].z + bE * e.z + bC * c.z + bN * n.z;
        o.w = ch * h[i].w + bE * e.w + bC * c.w + bN * n.w;
        __stcs(orow + idx, o);
    }
}

extern "C" void kernel_launch(void* const* d_in, const int* in_sizes, int n_in,
                              void* d_out, int out_size) {
    const float* h0 = (const float*)d_in[0];
    const float* aE = (const float*)d_in[1];
    const float* aC = (const float*)d_in[2];
    const float* aN = (const float*)d_in[3];
    float* out = (float*)d_out;

    anchor_stats_kernel<<<1, NTHREADS>>>(aE, aC, aN);
    collapse_kernel<<<BATCH, NTHREADS>>>(h0, aE, aC, aN, out);
}

// round 4
// speedup vs baseline: 1.4857x; 1.2284x over previous
#include <cuda_runtime.h>
#include <math.h>

#define DIM 4096
#define BATCH 8192
#define NUM_LAYERS 6
#define NTHREADS 256
#define VPT 4  // float4 per thread: 256 * 4 * 4 = 4096 floats

// g_stats layout: [0..2] inv_norm(E,C,N); [3..5] G00,G11,G22; [6..8] G01,G02,G12
__device__ float g_stats[9];

__device__ __forceinline__ float dot4(float4 a, float4 b) {
    return a.x * b.x + a.y * b.y + a.z * b.z + a.w * b.w;
}

// ---------------------------------------------------------------------------
// Kernel 0: anchor norms + normalized Gram matrix (one block, vectorized)
// ---------------------------------------------------------------------------
__global__ void anchor_stats_kernel(const float* __restrict__ aE,
                                    const float* __restrict__ aC,
                                    const float* __restrict__ aN) {
    __shared__ float red[6][NTHREADS / 32];
    float s[6] = {0.f, 0.f, 0.f, 0.f, 0.f, 0.f};
    const float4* e4 = (const float4*)aE;
    const float4* c4 = (const float4*)aC;
    const float4* n4 = (const float4*)aN;
#pragma unroll
    for (int i = 0; i < VPT; i++) {
        int idx = threadIdx.x + i * NTHREADS;
        float4 e = __ldg(e4 + idx);
        float4 c = __ldg(c4 + idx);
        float4 n = __ldg(n4 + idx);
        s[0] += dot4(e, e); s[1] += dot4(c, c); s[2] += dot4(n, n);
        s[3] += dot4(e, c); s[4] += dot4(e, n); s[5] += dot4(c, n);
    }
#pragma unroll
    for (int off = 16; off; off >>= 1) {
#pragma unroll
        for (int j = 0; j < 6; j++) s[j] += __shfl_xor_sync(0xffffffffu, s[j], off);
    }
    int warp = threadIdx.x >> 5, lane = threadIdx.x & 31;
    if (lane == 0) {
#pragma unroll
        for (int j = 0; j < 6; j++) red[j][warp] = s[j];
    }
    __syncthreads();
    if (threadIdx.x == 0) {
        float d[6];
#pragma unroll
        for (int j = 0; j < 6; j++) {
            float v = 0.f;
#pragma unroll
            for (int w = 0; w < NTHREADS / 32; w++) v += red[j][w];
            d[j] = v;
        }
        float i0 = 1.0f / fmaxf(sqrtf(d[0]), 1e-12f);
        float i1 = 1.0f / fmaxf(sqrtf(d[1]), 1e-12f);
        float i2 = 1.0f / fmaxf(sqrtf(d[2]), 1e-12f);
        g_stats[0] = i0; g_stats[1] = i1; g_stats[2] = i2;
        g_stats[3] = d[0] * i0 * i0;   // G00
        g_stats[4] = d[1] * i1 * i1;   // G11
        g_stats[5] = d[2] * i2 * i2;   // G22
        g_stats[6] = d[3] * i0 * i1;   // G01
        g_stats[7] = d[4] * i0 * i2;   // G02
        g_stats[8] = d[5] * i1 * i2;   // G12
    }
}

// ---------------------------------------------------------------------------
// Kernel 1: fused 6-layer collapse. One block = one row.
// Recurrence on warp 0 ONLY (fast-math); other warps idle at barrier,
// freeing issue slots for memory work of co-resident CTAs.
// ---------------------------------------------------------------------------
__global__ __launch_bounds__(NTHREADS, 4)
void collapse_kernel(const float* __restrict__ h0,
                     const float* __restrict__ aE,
                     const float* __restrict__ aC,
                     const float* __restrict__ aN,
                     float* __restrict__ out) {
    const int tid = threadIdx.x;
    const int b = blockIdx.x;

    __shared__ float red[4][NTHREADS / 32];
    __shared__ float bc[4];  // ch, bE, bC, bN

    float* outH = out;
    float* outA = out + (size_t)BATCH * DIM;
    float* outD = outA + (size_t)NUM_LAYERS * BATCH * 3;
    float* outT = outD + (size_t)NUM_LAYERS * BATCH * 3;

    const float4* hrow = (const float4*)(h0 + (size_t)b * DIM);
    const float4* e4 = (const float4*)aE;
    const float4* c4 = (const float4*)aC;
    const float4* n4 = (const float4*)aN;

    // h0 row lives in registers for the whole kernel (read-once: streaming hint)
    float4 h[VPT];
#pragma unroll
    for (int i = 0; i < VPT; i++) h[i] = __ldcs(hrow + tid + i * NTHREADS);

    // dot phase: anchors from L1 (48KB resident)
    float shh = 0.f, s0 = 0.f, s1 = 0.f, s2 = 0.f;
#pragma unroll
    for (int i = 0; i < VPT; i++) {
        int idx = tid + i * NTHREADS;
        float4 e = __ldg(e4 + idx);
        float4 c = __ldg(c4 + idx);
        float4 n = __ldg(n4 + idx);
        shh += dot4(h[i], h[i]);
        s0  += dot4(h[i], e);
        s1  += dot4(h[i], c);
        s2  += dot4(h[i], n);
    }

    // warp-level reduction, lane0 -> smem
#pragma unroll
    for (int off = 16; off; off >>= 1) {
        shh += __shfl_xor_sync(0xffffffffu, shh, off);
        s0  += __shfl_xor_sync(0xffffffffu, s0, off);
        s1  += __shfl_xor_sync(0xffffffffu, s1, off);
        s2  += __shfl_xor_sync(0xffffffffu, s2, off);
    }
    const int warp = tid >> 5, lane = tid & 31;
    if (lane == 0) { red[0][warp] = shh; red[1][warp] = s0; red[2][warp] = s1; red[3][warp] = s2; }
    __syncthreads();

    // --- warp 0 only: final sum + scalar 6-layer recurrence (fast math) ---
    if (warp == 0) {
        float hh = 0.f, t0 = 0.f, t1 = 0.f, t2 = 0.f;
#pragma unroll
        for (int w = 0; w < NTHREADS / 32; w++) {
            hh += red[0][w]; t0 += red[1][w]; t1 += red[2][w]; t2 += red[3][w];
        }
        const float invn0 = g_stats[0], invn1 = g_stats[1], invn2 = g_stats[2];
        const float G00 = g_stats[3], G11 = g_stats[4], G22 = g_stats[5];
        const float G01 = g_stats[6], G02 = g_stats[7], G12 = g_stats[8];

        float a0 = t0 * invn0, a1 = t1 * invn1, a2 = t2 * invn2;
        float ch = 1.f, c0 = 0.f, c1 = 0.f, c2 = 0.f;

#pragma unroll
        for (int l = 0; l < NUM_LAYERS; l++) {
            float invh = rsqrtf(fmaxf(hh, 1e-24f));
            float al0 = a0 * invh, al1 = a1 * invh, al2 = a2 * invh;
            float dv0 = 1.f - al0, dv1 = 1.f - al1, dv2 = 1.f - al2;
            if (lane == 0) {
                size_t o = ((size_t)l * BATCH + b) * 3;
                outA[o] = al0; outA[o + 1] = al1; outA[o + 2] = al2;
                outD[o] = dv0; outD[o + 1] = dv1; outD[o + 2] = dv2;
                outT[o] = fmaxf(dv0, 0.f); outT[o + 1] = fmaxf(dv1, 0.f); outT[o + 2] = fmaxf(dv2, 0.f);
            }
            // coef_k = s_k * div_k / ||h - dir_k||  (args O(1e3), rsqrt is safe)
            float k0 = 0.10f * dv0 * rsqrtf(fmaxf(hh - 2.f * a0 + G00, 1e-24f));
            float k1 = 0.10f * dv1 * rsqrtf(fmaxf(hh - 2.f * a1 + G11, 1e-24f));
            float k2 = 0.05f * dv2 * rsqrtf(fmaxf(hh - 2.f * a2 + G22, 1e-24f));
            float alpha = 1.f - (k0 + k1 + k2);

            float na0 = alpha * a0 + k0 * G00 + k1 * G01 + k2 * G02;
            float na1 = alpha * a1 + k0 * G01 + k1 * G11 + k2 * G12;
            float na2 = alpha * a2 + k0 * G02 + k1 * G12 + k2 * G22;
            float cross = k0 * k0 * G00 + k1 * k1 * G11 + k2 * k2 * G22
                        + 2.f * (k0 * k1 * G01 + k0 * k2 * G02 + k1 * k2 * G12);
            float nhh = alpha * alpha * hh
                      + 2.f * alpha * (k0 * a0 + k1 * a1 + k2 * a2) + cross;

            ch *= alpha;
            c0 = alpha * c0 + k0;
            c1 = alpha * c1 + k1;
            c2 = alpha * c2 + k2;
            hh = fmaxf(nhh, 0.f);
            a0 = na0; a1 = na1; a2 = na2;

            // norm clamp (uniform branch)
            float nn = sqrtf(hh);
            if (nn > 10.0f) {
                float sc = __fdividef(10.0f, nn + 1e-8f);
                ch *= sc; c0 *= sc; c1 *= sc; c2 *= sc;
                a0 *= sc; a1 *= sc; a2 *= sc;
                hh *= sc * sc;
            }
        }

        if (lane == 0) {
            bc[0] = ch;
            bc[1] = c0 * invn0;
            bc[2] = c1 * invn1;
            bc[3] = c2 * invn2;
        }
    }
    __syncthreads();

    // --- epilogue: h_final = ch*h0 + bE*aE + bC*aC + bN*aN ---
    const float ch = bc[0], bE = bc[1], bC = bc[2], bN = bc[3];
    float4* orow = (float4*)(outH + (size_t)b * DIM);
#pragma unroll
    for (int i = 0; i < VPT; i++) {
        int idx = tid + i * NTHREADS;
        float4 e = __ldg(e4 + idx);
        float4 c = __ldg(c4 + idx);
        float4 n = __ldg(n4 + idx);
        float4 o;
        o.x = ch * h[i].x + bE * e.x + bC * c.x + bN * n.x;
        o.y = ch * h[i].y + bE * e.y + bC * c.y + bN * n.y;
        o.z = ch * h[i].z + bE * e.z + bC * c.z + bN * n.z;
        o.w = ch * h[i].w + bE * e.w + bC * c.w + bN * n.w;
        __stcs(orow + idx, o);
    }
}

extern "C" void kernel_launch(void* const* d_in, const int* in_sizes, int n_in,
                              void* d_out, int out_size) {
    const float* h0 = (const float*)d_in[0];
    const float* aE = (const float*)d_in[1];
    const float* aC = (const float*)d_in[2];
    const float* aN = (const float*)d_in[3];
    float* out = (float*)d_out;

    anchor_stats_kernel<<<1, NTHREADS>>>(aE, aC, aN);
    collapse_kernel<<<BATCH, NTHREADS>>>(h0, aE, aC, aN, out);
}